// round 9
// baseline (speedup 1.0000x reference)
#include <cuda_runtime.h>
#include <math.h>

#define Nn 8
#define Cc 14
#define Hh 512
#define Ww 512
#define HW (Hh*Ww)
#define PIX (Nn*HW)
#define WPR 16

#define CW 148            // canny worker blocks (one per SM)
#define KD_PARTS 3
#define KD_BLOCKS (112*KD_PARTS)   // 336
#define GRID (CW + KD_BLOCKS)      // 484
#define Q4ALL (HW/4)               // 65536
#define Q4P 21846                  // ceil(65536/3)

// ---- scratch ----
__device__ unsigned char  g_tmap[PIX];
__device__ unsigned int   g_strongb[PIX/32];
__device__ unsigned int   g_weakb[PIX/32];
__device__ float          g_e[PIX];
__device__ float          g_part[KD_BLOCKS*3];
__device__ unsigned int   g_ctr[24*32];   // (img*3+phase)*32, padded to 128B lines
__device__ unsigned int   g_done;

// ---------- canny barrier among CW blocks ----------
__device__ __forceinline__ void cbar(int i) {
    __syncthreads();
    if (threadIdx.x == 0) {
        __threadfence();
        atomicAdd(&g_ctr[i * 32], 1u);
        while (*((volatile unsigned*)&g_ctr[i * 32]) < CW) __nanosleep(64);
        __threadfence();
    }
    __syncthreads();
}

// ---------- phase A: argmax for 8 px ----------
__device__ __forceinline__ void argmax_unit(const float* __restrict__ T, int img, int u) {
    const float4* base = (const float4*)(T + (size_t)img * Cc * HW) + u * 2;
    float best[8]; int id[8];
    {
        float4 a = base[0], b = base[1];
        best[0]=a.x; best[1]=a.y; best[2]=a.z; best[3]=a.w;
        best[4]=b.x; best[5]=b.y; best[6]=b.z; best[7]=b.w;
#pragma unroll
        for (int j = 0; j < 8; j++) id[j] = 0;
    }
#pragma unroll
    for (int c = 1; c < Cc; c++) {
        float4 a = base[(size_t)c * (HW / 4)];
        float4 b = base[(size_t)c * (HW / 4) + 1];
        float v[8] = {a.x,a.y,a.z,a.w,b.x,b.y,b.z,b.w};
#pragma unroll
        for (int j = 0; j < 8; j++)
            if (v[j] > best[j]) { best[j] = v[j]; id[j] = c; }
    }
    unsigned lo = 0, hi = 0;
#pragma unroll
    for (int j = 0; j < 4; j++) {
        lo |= (unsigned)((unsigned char)((float)id[j]     / 13.0f * 255.0f)) << (8*j);
        hi |= (unsigned)((unsigned char)((float)id[j + 4] / 13.0f * 255.0f)) << (8*j);
    }
    ((uint2*)g_tmap)[(size_t)img * (HW / 8) + u] = make_uint2(lo, hi);
}

// ---------- phase B: sobel+nms tile (32x32 core) ----------
__device__ void sobel_tile(unsigned* smu, int img, int t2, int tid) {
    unsigned char*  tm   = (unsigned char*)smu;          // 1296 B
    unsigned short* msec = (unsigned short*)(smu + 324); // 2312 B
    int ty0 = (t2 >> 4) * 32, tx0 = (t2 & 15) * 32;
    const unsigned char* base = g_tmap + (size_t)img * HW;
    for (int i = tid; i < 36*36; i += 256) {
        int ly = i / 36, lx = i % 36;
        int gy = ty0 + ly - 2; gy = gy < 0 ? 0 : (gy > 511 ? 511 : gy);
        int gx = tx0 + lx - 2; gx = gx < 0 ? 0 : (gx > 511 ? 511 : gx);
        tm[i] = base[gy * Ww + gx];
    }
    __syncthreads();
    for (int i = tid; i < 34*34; i += 256) {
        int ly = i / 34, lx = i % 34;
        const unsigned char* q = tm + ly * 36 + lx;
        int a0=q[0], a1=q[1], a2=q[2];
        int a3=q[36],          a5=q[38];
        int a6=q[72], a7=q[73], a8=q[74];
        int gx = (a2 + 2*a5 + a8) - (a0 + 2*a3 + a6);
        int gy = (a6 + 2*a7 + a8) - (a0 + 2*a1 + a2);
        int mag = abs(gx) + abs(gy);
        float fax = (float)abs(gx), fay = (float)abs(gy);
        int s;
        if (fay < 0.41421356f * fax)      s = 0;
        else if (fay < 2.41421356f * fax) s = ((gx ^ gy) >= 0) ? 1 : 3;
        else                              s = 2;
        msec[i] = (unsigned short)((mag << 2) | s);
    }
    __syncthreads();
#pragma unroll
    for (int k = 0; k < 4; k++) {
        int p = k * 256 + tid;
        int ly = p >> 5, lx = p & 31;
        int gy = ty0 + ly, gx = tx0 + lx;
        int v = msec[(ly+1)*34 + (lx+1)];
        int m = v >> 2, s = v & 3;
        int dy1, dx1, dy2, dx2;
        if (s == 0)      { dy1 = 0;  dx1 = 1;  dy2 = 0; dx2 = -1; }
        else if (s == 1) { dy1 = -1; dx1 = 1;  dy2 = 1; dx2 = -1; }
        else if (s == 2) { dy1 = -1; dx1 = 0;  dy2 = 1; dx2 = 0;  }
        else             { dy1 = -1; dx1 = -1; dy2 = 1; dx2 = 1;  }
        int y1 = gy + dy1, x1 = gx + dx1, y2 = gy + dy2, x2 = gx + dx2;
        int n1 = (y1 < 0 || y1 >= Hh || x1 < 0 || x1 >= Ww) ? 0
               : (msec[(ly+1+dy1)*34 + (lx+1+dx1)] >> 2);
        int n2 = (y2 < 0 || y2 >= Hh || x2 < 0 || x2 >= Ww) ? 0
               : (msec[(ly+1+dy2)*34 + (lx+1+dx2)] >> 2);
        int nms = (m >= n1 && m >= n2) ? m : 0;
        unsigned sm = __ballot_sync(0xffffffffu, nms > 50);
        unsigned wm = __ballot_sync(0xffffffffu, nms > 10);
        if (lx == 0) {
            int w = (img * Hh + gy) * WPR + (tx0 >> 5);
            g_strongb[w] = sm;
            g_weakb[w]   = wm;
        }
    }
    __syncthreads();
}

// ---------- phase C: hysteresis + dilate + blur, 64x64 tile ----------
#define TROWS 116
#define TW (TROWS*4)   // 464
__device__ void edge_tile(unsigned* smu, int img, int t, int tid) {
    unsigned* wk  = smu;
    unsigned* A   = smu + 464;
    unsigned* B   = smu + 928;
    unsigned* shp = smu + 1392;                // 74*16 = 1184 u32
    int ty = t >> 3, tx = t & 7;
    int y0  = ty * 64;
    int x0  = tx * 64;
    int gy0 = y0 - 26;
    int gw0 = tx * 2 - 1;
    for (int i = tid; i < TW; i += 256) {
        int row = i >> 2, wi = i & 3;
        int gy = gy0 + row, gw = gw0 + wi;
        bool in = (gy >= 0 && gy < Hh && gw >= 0 && gw < WPR);
        int idx = (img * Hh + gy) * WPR + gw;
        wk[i] = in ? g_weakb[idx]   : 0u;
        A[i]  = in ? g_strongb[idx] : 0u;
    }
    __syncthreads();
    unsigned* cur = A;
    unsigned* nxt = B;
    for (int it = 0; it < 16; it++) {
        for (int i = tid; i < TW; i += 256) {
            int row = i >> 2, wi = i & 3;
            unsigned out = 0;
#pragma unroll
            for (int dr = -1; dr <= 1; dr++) {
                int rr = row + dr;
                if ((unsigned)rr < TROWS) {
                    int b2 = rr * 4 + wi;
                    unsigned c = cur[b2];
                    unsigned l = wi       ? cur[b2 - 1] : 0u;
                    unsigned r = (wi < 3) ? cur[b2 + 1] : 0u;
                    out |= c | (c << 1) | (l >> 31) | (c >> 1) | (r << 31);
                }
            }
            nxt[i] = wk[i] & out;
        }
        __syncthreads();
        unsigned* tmp = cur; cur = nxt; nxt = tmp;
    }
    for (int i = tid; i < TW; i += 256) {
        int wi = i & 3;
        unsigned c = cur[i];
        unsigned l = wi       ? cur[i - 1] : 0u;
        unsigned r = (wi < 3) ? cur[i + 1] : 0u;
        unsigned long long lo = (unsigned long long)l | ((unsigned long long)c << 32);
        unsigned long long hi = (unsigned long long)c | ((unsigned long long)r << 32);
        unsigned o = 0;
#pragma unroll
        for (int d = 0; d <= 4; d++) o |= (unsigned)(hi >> d);
#pragma unroll
        for (int d = 1; d <= 5; d++) o |= (unsigned)(lo >> (32 - d));
        nxt[i] = o;
    }
    __syncthreads();
    for (int i = tid; i < 74 * 4; i += 256) {
        int rr = i >> 2, wi = i & 3;
        int row = 21 + rr;
        unsigned o = 0;
#pragma unroll
        for (int dy = -5; dy <= 4; dy++) o |= nxt[(row + dy) * 4 + wi];
        wk[i] = o;
    }
    __syncthreads();
    for (int i = tid; i < 74 * 16; i += 256) {
        int rr = i >> 4, g = i & 15;
        unsigned wv[4] = {wk[rr*4], wk[rr*4+1], wk[rr*4+2], wk[rr*4+3]};
        unsigned pack = 0;
#pragma unroll
        for (int jj = 0; jj < 4; jj++) {
            int j = g * 4 + jj;
            int x = x0 + j;
            int s;
            if (x >= 5 && x <= Ww - 5) {
                int p = 27 + j;
                int idx = p >> 5, off = p & 31;
                unsigned win = __funnelshift_r(wv[idx], wv[idx + 1 < 4 ? idx + 1 : 3], off);
                s = __popc(win & 0x3FFu);
            } else {
                s = 0;
                for (int dx = -5; dx <= 4; dx++) {
                    int xx = x + dx;
                    if (xx < 0) xx = -xx;
                    else if (xx >= Ww) xx = 2 * Ww - 2 - xx;
                    int bit = xx - x0 + 32;
                    s += (wv[bit >> 5] >> (bit & 31)) & 1;
                }
            }
            pack |= (unsigned)s << (8 * jj);
        }
        shp[i] = pack;
    }
    __syncthreads();
    for (int i = tid; i < 64 * 16; i += 256) {
        int ly = i >> 4, g = i & 15;
        int y = y0 + ly;
        unsigned acc = 0;
#pragma unroll
        for (int dy = -5; dy <= 4; dy++) {
            int yy = y + dy;
            if (yy < 0) yy = -yy;
            else if (yy >= Hh) yy = 2 * Hh - 2 - yy;
            acc += shp[(yy - y0 + 5) * 16 + g];
        }
        float4 o;
        o.x = rintf((float)(((acc      ) & 255u) * 255u) / 100.0f) / 255.0f;
        o.y = rintf((float)(((acc >> 8 ) & 255u) * 255u) / 100.0f) / 255.0f;
        o.z = rintf((float)(((acc >> 16) & 255u) * 255u) / 100.0f) / 255.0f;
        o.w = rintf((float)(((acc >> 24) & 255u) * 255u) / 100.0f) / 255.0f;
        *(float4*)(g_e + (size_t)img * HW + y * Ww + x0 + g * 4) = o;
    }
    __syncthreads();
}

// ---------- megakernel ----------
__global__ void __launch_bounds__(256, 4)
k_mega(const float* __restrict__ S, const float* __restrict__ T,
       float* __restrict__ out) {
    __shared__ unsigned smu[2592];   // union: edge 2576 u32 max
    __shared__ int is_last;
    int tid = threadIdx.x;
    int blk = blockIdx.x;

    if (blk < CW) {
        // ---------------- canny worker ----------------
        for (int img = 0; img < Nn; img++) {
            int u = blk * 256 + tid;
            if (u < HW / 8) argmax_unit(T, img, u);
            cbar(img * 3 + 0);
            for (int t2 = blk; t2 < 256; t2 += CW) sobel_tile(smu, img, t2, tid);
            cbar(img * 3 + 1);
            if (blk < 64) edge_tile(smu, img, blk, tid);
            cbar(img * 3 + 2);     // completion flag for image img
        }
        return;
    }

    // ---------------- kd worker ----------------
    int kidx = blk - CW;              // 0..335
    int r = kidx / KD_PARTS;          // (n,c) 0..111
    int part = kidx % KD_PARTS;
    int n = r / Cc, c = r % Cc;

    // wait for edges of image n
    if (tid == 0) {
        while (*((volatile unsigned*)&g_ctr[(n * 3 + 2) * 32]) < CW) __nanosleep(256);
        __threadfence();
    }
    __syncthreads();

    const float4* e4 = (const float4*)(g_e + (size_t)n * HW);
    const float4* t4 = (const float4*)(T + ((size_t)n * Cc + c) * HW);
    const float4* s4 = (const float4*)(S + ((size_t)n * Cc + c) * HW);
    const int kbeg = part * Q4P;
    const int kend = (kbeg + Q4P < Q4ALL) ? kbeg + Q4P : Q4ALL;

    float zt = 0.f, st = 0.f, zs = 0.f;
#pragma unroll 2
    for (int k = kbeg + tid; k < kend; k += 256) {
        float4 ev = e4[k];
        float4 tv = t4[k];
        float4 sv = s4[k];
        float el[4] = {ev.x, ev.y, ev.z, ev.w};
        float tl[4] = {tv.x, tv.y, tv.z, tv.w};
        float sl[4] = {sv.x, sv.y, sv.z, sv.w};
#pragma unroll
        for (int j = 0; j < 4; j++) {
            float xt = el[j] * tl[j];
            float xs = el[j] * sl[j];
            float et = __expf(xt);
            zt += et;
            zs += __expf(xs);
            st += et * (xt - xs);
        }
    }
    float* r1 = (float*)smu;
    float* r2 = r1 + 256;
    float* r3 = r1 + 512;
    r1[tid] = zt; r2[tid] = st; r3[tid] = zs;
    __syncthreads();
    for (int off = 128; off > 0; off >>= 1) {
        if (tid < off) {
            r1[tid] += r1[tid + off];
            r2[tid] += r2[tid + off];
            r3[tid] += r3[tid + off];
        }
        __syncthreads();
    }
    if (tid == 0) {
        float* q = &g_part[kidx * 3];
        q[0] = r1[0]; q[1] = r2[0]; q[2] = r3[0];
        __threadfence();
        unsigned v = atomicAdd(&g_done, 1u);
        is_last = (v == (unsigned)(KD_BLOCKS - 1));
    }
    __syncthreads();
    if (!is_last) return;
    __threadfence();
    // final reduction: 112 rows x 3 parts
    float term = 0.0f;
    if (tid < 112) {
        float azt = 0.f, ast = 0.f, azs = 0.f;
        const float* q = &g_part[tid * KD_PARTS * 3];
#pragma unroll
        for (int p = 0; p < KD_PARTS; p++) {
            azt += q[p*3]; ast += q[p*3+1]; azs += q[p*3+2];
        }
        term = ast / azt - logf(azt) + logf(azs);
    }
    __syncthreads();        // r1 free for reuse
    r1[tid] = term;
    __syncthreads();
    for (int off = 128; off > 0; off >>= 1) {
        if (tid < off) r1[tid] += r1[tid + off];
        __syncthreads();
    }
    if (tid == 0) {
        out[0] = r1[0] / 112.0f;
        // reset all coordination state for the next (graph-replayed) run
#pragma unroll
        for (int i = 0; i < 24; i++) g_ctr[i * 32] = 0;
        g_done = 0;
    }
}

// ---------------- launch ----------------
extern "C" void kernel_launch(void* const* d_in, const int* in_sizes, int n_in,
                              void* d_out, int out_size) {
    const float* S = (const float*)d_in[0];
    const float* T = (const float*)d_in[1];
    float* out = (float*)d_out;
    k_mega<<<GRID, 256>>>(S, T, out);
}

// round 10
// speedup vs baseline: 3.0385x; 3.0385x over previous
#include <cuda_runtime.h>
#include <math.h>

#define Nn 8
#define Cc 14
#define Hh 512
#define Ww 512
#define HW (Hh*Ww)
#define PIX (Nn*HW)
#define ROWS (Nn*Cc)   // 112
#define PARTS 8
#define WPR 16         // 512-bit row = 16 u32 words

// ---- scratch ----
__device__ unsigned char  g_tmap[PIX];
__device__ unsigned int   g_strongb[PIX/32];
__device__ unsigned int   g_weakb[PIX/32];
__device__ float          g_e[PIX];
__device__ float          g_part[ROWS*PARTS*3];
__device__ unsigned int   g_done;   // zero-init; reset by last block each launch

// pack index into low 4 mantissa bits: (bits & ~15) | idx  -- single LOP3
__device__ __forceinline__ float packed(float x, unsigned idxreg) {
    unsigned b = __float_as_uint(x), o;
    asm("lop3.b32 %0, %1, 0xFFFFFFF0, %2, 0xEA;" : "=r"(o) : "r"(b), "r"(idxreg));
    return __uint_as_float(o);
}

// ---------------- 1. teacher argmax via index-packed FMNMX (8 px/thread) ----------------
__global__ void k_argmax(const float* __restrict__ T) {
    int p8 = blockIdx.x * blockDim.x + threadIdx.x;
    if (p8 >= PIX / 8) return;
    int n = p8 / (HW / 8), sp8 = p8 % (HW / 8);
    const float4* base = (const float4*)(T + (size_t)n * Cc * HW) + sp8 * 2;
    float best[8];
    {
        float4 a = base[0], b = base[1];
        float v[8] = {a.x,a.y,a.z,a.w,b.x,b.y,b.z,b.w};
#pragma unroll
        for (int j = 0; j < 8; j++) best[j] = packed(v[j], 13u);   // c=0 -> idx 13
    }
#pragma unroll
    for (int c = 1; c < Cc; c++) {
        float4 a = base[(size_t)c * (HW / 4)];
        float4 b = base[(size_t)c * (HW / 4) + 1];
        float v[8] = {a.x,a.y,a.z,a.w,b.x,b.y,b.z,b.w};
        unsigned idx = (unsigned)(13 - c);
#pragma unroll
        for (int j = 0; j < 8; j++) best[j] = fmaxf(best[j], packed(v[j], idx));
    }
    unsigned lo = 0, hi = 0;
#pragma unroll
    for (int j = 0; j < 4; j++) {
        int c0 = 13 - (int)(__float_as_uint(best[j])     & 15u);
        int c1 = 13 - (int)(__float_as_uint(best[j + 4]) & 15u);
        lo |= (unsigned)((unsigned char)((float)c0 / 13.0f * 255.0f)) << (8*j);
        hi |= (unsigned)((unsigned char)((float)c1 / 13.0f * 255.0f)) << (8*j);
    }
    ((uint2*)g_tmap)[p8] = make_uint2(lo, hi);
}

// ---------------- 2. fused Sobel + NMS (branch-free sectors) ----------------
__global__ void k_sobel_nms() {
    __shared__ unsigned char tm[36*36];
    __shared__ unsigned short msec[34*34];   // mag<<2 | sect
    int img = blockIdx.x >> 8;
    int t   = blockIdx.x & 255;
    int ty0 = (t >> 4) * 32, tx0 = (t & 15) * 32;
    int tid = threadIdx.x;
    const unsigned char* base = g_tmap + img * HW;
    for (int i = tid; i < 36*36; i += 256) {
        int ly = i / 36, lx = i % 36;
        int gy = ty0 + ly - 2; gy = gy < 0 ? 0 : (gy > 511 ? 511 : gy);
        int gx = tx0 + lx - 2; gx = gx < 0 ? 0 : (gx > 511 ? 511 : gx);
        tm[i] = base[gy * Ww + gx];
    }
    __syncthreads();
    for (int i = tid; i < 34*34; i += 256) {
        int ly = i / 34, lx = i % 34;
        const unsigned char* q = tm + ly * 36 + lx;
        int a0=q[0], a1=q[1], a2=q[2];
        int a3=q[36],          a5=q[38];
        int a6=q[72], a7=q[73], a8=q[74];
        int gx = (a2 + 2*a5 + a8) - (a0 + 2*a3 + a6);
        int gy = (a6 + 2*a7 + a8) - (a0 + 2*a1 + a2);
        int mag = abs(gx) + abs(gy);
        float fax = (float)abs(gx), fay = (float)abs(gy);
        int s;
        if (fay < 0.41421356f * fax)      s = 0;
        else if (fay < 2.41421356f * fax) s = ((gx ^ gy) >= 0) ? 1 : 3;
        else                              s = 2;
        msec[i] = (unsigned short)((mag << 2) | s);
    }
    __syncthreads();
#pragma unroll
    for (int k = 0; k < 4; k++) {
        int p = k * 256 + tid;
        int ly = p >> 5, lx = p & 31;
        int gy = ty0 + ly, gx = tx0 + lx;
        int v = msec[(ly+1)*34 + (lx+1)];
        int m = v >> 2, s = v & 3;
        int dy1, dx1, dy2, dx2;
        if (s == 0)      { dy1 = 0;  dx1 = 1;  dy2 = 0; dx2 = -1; }
        else if (s == 1) { dy1 = -1; dx1 = 1;  dy2 = 1; dx2 = -1; }
        else if (s == 2) { dy1 = -1; dx1 = 0;  dy2 = 1; dx2 = 0;  }
        else             { dy1 = -1; dx1 = -1; dy2 = 1; dx2 = 1;  }
        int y1 = gy + dy1, x1 = gx + dx1, y2 = gy + dy2, x2 = gx + dx2;
        int n1 = (y1 < 0 || y1 >= Hh || x1 < 0 || x1 >= Ww) ? 0
               : (msec[(ly+1+dy1)*34 + (lx+1+dx1)] >> 2);
        int n2 = (y2 < 0 || y2 >= Hh || x2 < 0 || x2 >= Ww) ? 0
               : (msec[(ly+1+dy2)*34 + (lx+1+dx2)] >> 2);
        int nms = (m >= n1 && m >= n2) ? m : 0;
        unsigned sm = __ballot_sync(0xffffffffu, nms > 50);
        unsigned wm = __ballot_sync(0xffffffffu, nms > 10);
        if (lx == 0) {
            int w = (img * Hh + gy) * WPR + (tx0 >> 5);
            g_strongb[w] = sm;
            g_weakb[w]   = wm;
        }
    }
}

// ---------------- 3. hysteresis(16) + dilate 10x10 + blur 10x10, one kernel ----------------
#define TROWS 116
#define TW (TROWS*4)   // 464
__global__ void k_edge() {
    __shared__ unsigned wk[TW], A[TW], B[TW];
    __shared__ unsigned shp[74*16];
    int img = blockIdx.x >> 6;
    int t   = blockIdx.x & 63;
    int ty = t >> 3, tx = t & 7;
    int y0  = ty * 64;
    int x0  = tx * 64;
    int gy0 = y0 - 26;
    int gw0 = tx * 2 - 1;
    int tid = threadIdx.x;
    for (int i = tid; i < TW; i += 256) {
        int row = i >> 2, wi = i & 3;
        int gy = gy0 + row, gw = gw0 + wi;
        bool in = (gy >= 0 && gy < Hh && gw >= 0 && gw < WPR);
        int idx = (img * Hh + gy) * WPR + gw;
        wk[i] = in ? g_weakb[idx]   : 0u;
        A[i]  = in ? g_strongb[idx] : 0u;
    }
    __syncthreads();
    unsigned* cur = A;
    unsigned* nxt = B;
    for (int it = 0; it < 16; it++) {
        for (int i = tid; i < TW; i += 256) {
            int row = i >> 2, wi = i & 3;
            unsigned out = 0;
#pragma unroll
            for (int dr = -1; dr <= 1; dr++) {
                int rr = row + dr;
                if ((unsigned)rr < TROWS) {
                    int b2 = rr * 4 + wi;
                    unsigned c = cur[b2];
                    unsigned l = wi       ? cur[b2 - 1] : 0u;
                    unsigned r = (wi < 3) ? cur[b2 + 1] : 0u;
                    out |= c | (c << 1) | (l >> 31) | (c >> 1) | (r << 31);
                }
            }
            nxt[i] = wk[i] & out;
        }
        __syncthreads();
        unsigned* tmp = cur; cur = nxt; nxt = tmp;
    }
    for (int i = tid; i < TW; i += 256) {
        int wi = i & 3;
        unsigned c = cur[i];
        unsigned l = wi       ? cur[i - 1] : 0u;
        unsigned r = (wi < 3) ? cur[i + 1] : 0u;
        unsigned long long lo = (unsigned long long)l | ((unsigned long long)c << 32);
        unsigned long long hi = (unsigned long long)c | ((unsigned long long)r << 32);
        unsigned o = 0;
#pragma unroll
        for (int d = 0; d <= 4; d++) o |= (unsigned)(hi >> d);
#pragma unroll
        for (int d = 1; d <= 5; d++) o |= (unsigned)(lo >> (32 - d));
        nxt[i] = o;
    }
    __syncthreads();
    for (int i = tid; i < 74 * 4; i += 256) {
        int rr = i >> 2, wi = i & 3;
        int row = 21 + rr;
        unsigned o = 0;
#pragma unroll
        for (int dy = -5; dy <= 4; dy++) o |= nxt[(row + dy) * 4 + wi];
        wk[i] = o;
    }
    __syncthreads();
    for (int i = tid; i < 74 * 16; i += 256) {
        int rr = i >> 4, g = i & 15;
        unsigned wv[4] = {wk[rr*4], wk[rr*4+1], wk[rr*4+2], wk[rr*4+3]};
        unsigned pack = 0;
#pragma unroll
        for (int jj = 0; jj < 4; jj++) {
            int j = g * 4 + jj;
            int x = x0 + j;
            int s;
            if (x >= 5 && x <= Ww - 5) {
                int p = 27 + j;
                int idx = p >> 5, off = p & 31;
                unsigned win = __funnelshift_r(wv[idx], wv[idx + 1 < 4 ? idx + 1 : 3], off);
                s = __popc(win & 0x3FFu);
            } else {
                s = 0;
                for (int dx = -5; dx <= 4; dx++) {
                    int xx = x + dx;
                    if (xx < 0) xx = -xx;
                    else if (xx >= Ww) xx = 2 * Ww - 2 - xx;
                    int bit = xx - x0 + 32;
                    s += (wv[bit >> 5] >> (bit & 31)) & 1;
                }
            }
            pack |= (unsigned)s << (8 * jj);
        }
        shp[i] = pack;
    }
    __syncthreads();
    for (int i = tid; i < 64 * 16; i += 256) {
        int ly = i >> 4, g = i & 15;
        int y = y0 + ly;
        unsigned acc = 0;
#pragma unroll
        for (int dy = -5; dy <= 4; dy++) {
            int yy = y + dy;
            if (yy < 0) yy = -yy;
            else if (yy >= Hh) yy = 2 * Hh - 2 - yy;
            acc += shp[(yy - y0 + 5) * 16 + g];
        }
        float4 o;
        o.x = rintf((float)(((acc      ) & 255u) * 255u) / 100.0f) / 255.0f;
        o.y = rintf((float)(((acc >> 8 ) & 255u) * 255u) / 100.0f) / 255.0f;
        o.z = rintf((float)(((acc >> 16) & 255u) * 255u) / 100.0f) / 255.0f;
        o.w = rintf((float)(((acc >> 24) & 255u) * 255u) / 100.0f) / 255.0f;
        *(float4*)(g_e + (size_t)img * HW + y * Ww + x0 + g * 4) = o;
    }
}

// ---------------- 4. masked channel-softmax KL + fused final reduction ----------------
__global__ void k_kd(const float* __restrict__ S, const float* __restrict__ T,
                     float* __restrict__ out) {
    int r = blockIdx.x;                 // (n,c)
    int part = blockIdx.y;
    int n = r / Cc, c = r % Cc;
    const float4* e4 = (const float4*)(g_e + (size_t)n * HW);
    const float4* t4 = (const float4*)(T + ((size_t)n * Cc + c) * HW);
    const float4* s4 = (const float4*)(S + ((size_t)n * Cc + c) * HW);
    const int q4 = HW / 4 / PARTS;      // 8192
    const int base = part * q4;
    int tid = threadIdx.x;

    float zt = 0.f, st = 0.f, zs = 0.f;
#pragma unroll 2
    for (int k = tid; k < q4; k += blockDim.x) {
        float4 ev = e4[base + k];
        float4 tv = __ldcs(&t4[base + k]);   // single-use stream: evict-first
        float4 sv = __ldcs(&s4[base + k]);
        float el[4] = {ev.x, ev.y, ev.z, ev.w};
        float tl[4] = {tv.x, tv.y, tv.z, tv.w};
        float sl[4] = {sv.x, sv.y, sv.z, sv.w};
#pragma unroll
        for (int j = 0; j < 4; j++) {
            float xt = el[j] * tl[j];
            float xs = el[j] * sl[j];
            float et = __expf(xt);
            zt += et;
            zs += __expf(xs);
            st += et * (xt - xs);
        }
    }
    __shared__ float r1[256], r2[256], r3[256];
    r1[tid] = zt; r2[tid] = st; r3[tid] = zs;
    __syncthreads();
    for (int off = 128; off > 0; off >>= 1) {
        if (tid < off) {
            r1[tid] += r1[tid + off];
            r2[tid] += r2[tid + off];
            r3[tid] += r3[tid + off];
        }
        __syncthreads();
    }
    __shared__ int is_last;
    if (tid == 0) {
        float* q = &g_part[(r * PARTS + part) * 3];
        q[0] = r1[0]; q[1] = r2[0]; q[2] = r3[0];
        __threadfence();
        unsigned v = atomicAdd(&g_done, 1u);
        is_last = (v == (unsigned)(ROWS * PARTS - 1));
    }
    __syncthreads();
    if (!is_last) return;
    __threadfence();                    // acquire all g_part writes
    float term = 0.0f;
    if (tid < ROWS) {
        float azt = 0.f, ast = 0.f, azs = 0.f;
        const float* q = &g_part[tid * PARTS * 3];
#pragma unroll
        for (int p = 0; p < PARTS; p++) {
            azt += q[p*3]; ast += q[p*3+1]; azs += q[p*3+2];
        }
        term = ast / azt - logf(azt) + logf(azs);
    }
    r1[tid] = term;
    __syncthreads();
    for (int off = 128; off > 0; off >>= 1) {
        if (tid < off) r1[tid] += r1[tid + off];
        __syncthreads();
    }
    if (tid == 0) {
        out[0] = r1[0] / 112.0f;
        g_done = 0;                     // reset for next graph replay
    }
}

// ---------------- launch ----------------
extern "C" void kernel_launch(void* const* d_in, const int* in_sizes, int n_in,
                              void* d_out, int out_size) {
    const float* S = (const float*)d_in[0];
    const float* T = (const float*)d_in[1];
    float* out = (float*)d_out;

    k_argmax<<<PIX / 8 / 256, 256>>>(T);
    k_sobel_nms<<<Nn * 256, 256>>>();
    k_edge<<<Nn * 64, 256>>>();
    dim3 g(ROWS, PARTS);
    k_kd<<<g, 256>>>(S, T, out);
}

// round 12
// speedup vs baseline: 3.4592x; 1.1385x over previous
#include <cuda_runtime.h>
#include <math.h>

#define Nn 8
#define Cc 14
#define Hh 512
#define Ww 512
#define HW (Hh*Ww)
#define PIX (Nn*HW)
#define PARTS 8
#define TOTBLK (Nn*Cc*PARTS)   // 896
#define WPR 16

// role bid ranges
#define ARG0 0
#define SOB0 1024
#define EDGE0 3072
#define KD0  3584
#define GRID 4480

// ---- scratch ----
__device__ unsigned char  g_tmap[PIX];
__device__ unsigned int   g_strongb[PIX/32];
__device__ unsigned int   g_weakb[PIX/32];
__device__ float          g_e[PIX];
__device__ float          g_part[TOTBLK*3];
__device__ unsigned int   g_ctr[24*32];    // (img*3+phase)*32, 128B padded
__device__ unsigned int   g_done;          // reset by final block each launch

__device__ __forceinline__ void release_ctr(int idx) {
    __syncthreads();
    if (threadIdx.x == 0) {
        __threadfence();
        atomicAdd(&g_ctr[idx * 32], 1u);
    }
}
__device__ __forceinline__ void wait_ctr(int idx, unsigned target) {
    if (threadIdx.x == 0) {
        while (*((volatile unsigned*)&g_ctr[idx * 32]) < target) __nanosleep(128);
        __threadfence();
    }
    __syncthreads();
}

// pack index into low 4 mantissa bits -- single LOP3
__device__ __forceinline__ float packed(float x, unsigned idxreg) {
    unsigned b = __float_as_uint(x), o;
    asm("lop3.b32 %0, %1, 0xFFFFFFF0, %2, 0xEA;" : "=r"(o) : "r"(b), "r"(idxreg));
    return __uint_as_float(o);
}

// ---------- role A: argmax, 8 px/thread ----------
__device__ __forceinline__ void argmax_unit(const float* __restrict__ T, int img, int u) {
    const float4* base = (const float4*)(T + (size_t)img * Cc * HW) + u * 2;
    float best[8];
    {
        float4 a = base[0], b = base[1];
        float v[8] = {a.x,a.y,a.z,a.w,b.x,b.y,b.z,b.w};
#pragma unroll
        for (int j = 0; j < 8; j++) best[j] = packed(v[j], 13u);
    }
#pragma unroll
    for (int c = 1; c < Cc; c++) {
        float4 a = base[(size_t)c * (HW / 4)];
        float4 b = base[(size_t)c * (HW / 4) + 1];
        float v[8] = {a.x,a.y,a.z,a.w,b.x,b.y,b.z,b.w};
        unsigned idx = (unsigned)(13 - c);
#pragma unroll
        for (int j = 0; j < 8; j++) best[j] = fmaxf(best[j], packed(v[j], idx));
    }
    unsigned lo = 0, hi = 0;
#pragma unroll
    for (int j = 0; j < 4; j++) {
        int c0 = 13 - (int)(__float_as_uint(best[j])     & 15u);
        int c1 = 13 - (int)(__float_as_uint(best[j + 4]) & 15u);
        lo |= (unsigned)((unsigned char)((float)c0 / 13.0f * 255.0f)) << (8*j);
        hi |= (unsigned)((unsigned char)((float)c1 / 13.0f * 255.0f)) << (8*j);
    }
    ((uint2*)g_tmap)[(size_t)img * (HW / 8) + u] = make_uint2(lo, hi);
}

// ---------- role B: sobel+nms 32x32 tile ----------
__device__ void sobel_tile(unsigned* smu, int img, int t2, int tid) {
    unsigned char*  tm   = (unsigned char*)smu;
    unsigned short* msec = (unsigned short*)(smu + 324);
    int ty0 = (t2 >> 4) * 32, tx0 = (t2 & 15) * 32;
    const unsigned char* base = g_tmap + (size_t)img * HW;
    for (int i = tid; i < 36*36; i += 256) {
        int ly = i / 36, lx = i % 36;
        int gy = ty0 + ly - 2; gy = gy < 0 ? 0 : (gy > 511 ? 511 : gy);
        int gx = tx0 + lx - 2; gx = gx < 0 ? 0 : (gx > 511 ? 511 : gx);
        tm[i] = base[gy * Ww + gx];
    }
    __syncthreads();
    for (int i = tid; i < 34*34; i += 256) {
        int ly = i / 34, lx = i % 34;
        const unsigned char* q = tm + ly * 36 + lx;
        int a0=q[0], a1=q[1], a2=q[2];
        int a3=q[36],          a5=q[38];
        int a6=q[72], a7=q[73], a8=q[74];
        int gx = (a2 + 2*a5 + a8) - (a0 + 2*a3 + a6);
        int gy = (a6 + 2*a7 + a8) - (a0 + 2*a1 + a2);
        int mag = abs(gx) + abs(gy);
        float fax = (float)abs(gx), fay = (float)abs(gy);
        int s;
        if (fay < 0.41421356f * fax)      s = 0;
        else if (fay < 2.41421356f * fax) s = ((gx ^ gy) >= 0) ? 1 : 3;
        else                              s = 2;
        msec[i] = (unsigned short)((mag << 2) | s);
    }
    __syncthreads();
#pragma unroll
    for (int k = 0; k < 4; k++) {
        int p = k * 256 + tid;
        int ly = p >> 5, lx = p & 31;
        int gy = ty0 + ly, gx = tx0 + lx;
        int v = msec[(ly+1)*34 + (lx+1)];
        int m = v >> 2, s = v & 3;
        int dy1, dx1, dy2, dx2;
        if (s == 0)      { dy1 = 0;  dx1 = 1;  dy2 = 0; dx2 = -1; }
        else if (s == 1) { dy1 = -1; dx1 = 1;  dy2 = 1; dx2 = -1; }
        else if (s == 2) { dy1 = -1; dx1 = 0;  dy2 = 1; dx2 = 0;  }
        else             { dy1 = -1; dx1 = -1; dy2 = 1; dx2 = 1;  }
        int y1 = gy + dy1, x1 = gx + dx1, y2 = gy + dy2, x2 = gx + dx2;
        int n1 = (y1 < 0 || y1 >= Hh || x1 < 0 || x1 >= Ww) ? 0
               : (msec[(ly+1+dy1)*34 + (lx+1+dx1)] >> 2);
        int n2 = (y2 < 0 || y2 >= Hh || x2 < 0 || x2 >= Ww) ? 0
               : (msec[(ly+1+dy2)*34 + (lx+1+dx2)] >> 2);
        int nms = (m >= n1 && m >= n2) ? m : 0;
        unsigned sm = __ballot_sync(0xffffffffu, nms > 50);
        unsigned wm = __ballot_sync(0xffffffffu, nms > 10);
        if (lx == 0) {
            int w = (img * Hh + gy) * WPR + (tx0 >> 5);
            g_strongb[w] = sm;
            g_weakb[w]   = wm;
        }
    }
}

// ---------- role C: hysteresis + dilate + blur, 64x64 tile ----------
#define TROWS 116
#define TW (TROWS*4)
__device__ void edge_tile(unsigned* smu, int img, int t, int tid) {
    unsigned* wk  = smu;
    unsigned* A   = smu + 464;
    unsigned* B   = smu + 928;
    unsigned* shp = smu + 1392;
    int ty = t >> 3, tx = t & 7;
    int y0  = ty * 64;
    int x0  = tx * 64;
    int gy0 = y0 - 26;
    int gw0 = tx * 2 - 1;
    for (int i = tid; i < TW; i += 256) {
        int row = i >> 2, wi = i & 3;
        int gy = gy0 + row, gw = gw0 + wi;
        bool in = (gy >= 0 && gy < Hh && gw >= 0 && gw < WPR);
        int idx = (img * Hh + gy) * WPR + gw;
        wk[i] = in ? g_weakb[idx]   : 0u;
        A[i]  = in ? g_strongb[idx] : 0u;
    }
    __syncthreads();
    unsigned* cur = A;
    unsigned* nxt = B;
    for (int it = 0; it < 16; it++) {
        for (int i = tid; i < TW; i += 256) {
            int row = i >> 2, wi = i & 3;
            unsigned out = 0;
#pragma unroll
            for (int dr = -1; dr <= 1; dr++) {
                int rr = row + dr;
                if ((unsigned)rr < TROWS) {
                    int b2 = rr * 4 + wi;
                    unsigned c = cur[b2];
                    unsigned l = wi       ? cur[b2 - 1] : 0u;
                    unsigned r = (wi < 3) ? cur[b2 + 1] : 0u;
                    out |= c | (c << 1) | (l >> 31) | (c >> 1) | (r << 31);
                }
            }
            nxt[i] = wk[i] & out;
        }
        __syncthreads();
        unsigned* tmp = cur; cur = nxt; nxt = tmp;
    }
    for (int i = tid; i < TW; i += 256) {
        int wi = i & 3;
        unsigned c = cur[i];
        unsigned l = wi       ? cur[i - 1] : 0u;
        unsigned r = (wi < 3) ? cur[i + 1] : 0u;
        unsigned long long lo = (unsigned long long)l | ((unsigned long long)c << 32);
        unsigned long long hi = (unsigned long long)c | ((unsigned long long)r << 32);
        unsigned o = 0;
#pragma unroll
        for (int d = 0; d <= 4; d++) o |= (unsigned)(hi >> d);
#pragma unroll
        for (int d = 1; d <= 5; d++) o |= (unsigned)(lo >> (32 - d));
        nxt[i] = o;
    }
    __syncthreads();
    for (int i = tid; i < 74 * 4; i += 256) {
        int rr = i >> 2, wi = i & 3;
        int row = 21 + rr;
        unsigned o = 0;
#pragma unroll
        for (int dy = -5; dy <= 4; dy++) o |= nxt[(row + dy) * 4 + wi];
        wk[i] = o;
    }
    __syncthreads();
    for (int i = tid; i < 74 * 16; i += 256) {
        int rr = i >> 4, g = i & 15;
        unsigned wv[4] = {wk[rr*4], wk[rr*4+1], wk[rr*4+2], wk[rr*4+3]};
        unsigned pack = 0;
#pragma unroll
        for (int jj = 0; jj < 4; jj++) {
            int j = g * 4 + jj;
            int x = x0 + j;
            int s;
            if (x >= 5 && x <= Ww - 5) {
                int p = 27 + j;
                int idx = p >> 5, off = p & 31;
                unsigned win = __funnelshift_r(wv[idx], wv[idx + 1 < 4 ? idx + 1 : 3], off);
                s = __popc(win & 0x3FFu);
            } else {
                s = 0;
                for (int dx = -5; dx <= 4; dx++) {
                    int xx = x + dx;
                    if (xx < 0) xx = -xx;
                    else if (xx >= Ww) xx = 2 * Ww - 2 - xx;
                    int bit = xx - x0 + 32;
                    s += (wv[bit >> 5] >> (bit & 31)) & 1;
                }
            }
            pack |= (unsigned)s << (8 * jj);
        }
        shp[i] = pack;
    }
    __syncthreads();
    for (int i = tid; i < 64 * 16; i += 256) {
        int ly = i >> 4, g = i & 15;
        int y = y0 + ly;
        unsigned acc = 0;
#pragma unroll
        for (int dy = -5; dy <= 4; dy++) {
            int yy = y + dy;
            if (yy < 0) yy = -yy;
            else if (yy >= Hh) yy = 2 * Hh - 2 - yy;
            acc += shp[(yy - y0 + 5) * 16 + g];
        }
        float4 o;
        o.x = rintf((float)(((acc      ) & 255u) * 255u) / 100.0f) / 255.0f;
        o.y = rintf((float)(((acc >> 8 ) & 255u) * 255u) / 100.0f) / 255.0f;
        o.z = rintf((float)(((acc >> 16) & 255u) * 255u) / 100.0f) / 255.0f;
        o.w = rintf((float)(((acc >> 24) & 255u) * 255u) / 100.0f) / 255.0f;
        *(float4*)(g_e + (size_t)img * HW + y * Ww + x0 + g * 4) = o;
    }
}

// ---------- fused pipeline kernel ----------
__global__ void __launch_bounds__(256, 6)
k_all(const float* __restrict__ S, const float* __restrict__ T,
      float* __restrict__ out) {
    __shared__ unsigned smu[2592];
    __shared__ int is_last;
    int bid = blockIdx.x;
    int tid = threadIdx.x;

    if (bid < SOB0) {
        int img = bid >> 7;                    // 128 blocks/img
        int u = ((bid & 127) << 8) + tid;      // exactly HW/8 units/img
        argmax_unit(T, img, u);
        release_ctr(img * 3 + 0);
        return;
    }
    if (bid < EDGE0) {
        int sb = bid - SOB0;
        int img = sb >> 8, t = sb & 255;
        wait_ctr(img * 3 + 0, 128);
        sobel_tile(smu, img, t, tid);
        release_ctr(img * 3 + 1);
        return;
    }
    if (bid < KD0) {
        int eb = bid - EDGE0;
        int img = eb >> 6, t = eb & 63;
        wait_ctr(img * 3 + 1, 256);
        edge_tile(smu, img, t, tid);
        release_ctr(img * 3 + 2);
        return;
    }

    // ---------- role D: kd ----------
    int kb = bid - KD0;                 // 0..895
    int img = kb / (Cc * PARTS);
    int rem = kb % (Cc * PARTS);
    int c = rem / PARTS;
    int part = rem % PARTS;
    wait_ctr(img * 3 + 2, 64);

    const float4* e4 = (const float4*)(g_e + (size_t)img * HW);
    const float4* t4 = (const float4*)(T + ((size_t)img * Cc + c) * HW);
    const float4* s4 = (const float4*)(S + ((size_t)img * Cc + c) * HW);
    const int q4 = HW / 4 / PARTS;      // 8192
    const int base = part * q4;

    float zt = 0.f, st = 0.f, zs = 0.f;
#pragma unroll 2
    for (int k = tid; k < q4; k += 256) {
        float4 ev = e4[base + k];
        float4 tv = __ldcs(&t4[base + k]);
        float4 sv = __ldcs(&s4[base + k]);
        float el[4] = {ev.x, ev.y, ev.z, ev.w};
        float tl[4] = {tv.x, tv.y, tv.z, tv.w};
        float sl[4] = {sv.x, sv.y, sv.z, sv.w};
#pragma unroll
        for (int j = 0; j < 4; j++) {
            float xt = el[j] * tl[j];
            float xs = el[j] * sl[j];
            float et = __expf(xt);
            zt += et;
            zs += __expf(xs);
            st += et * (xt - xs);
        }
    }
    float* r1 = (float*)smu;
    float* r2 = r1 + 256;
    float* r3 = r1 + 512;
    r1[tid] = zt; r2[tid] = st; r3[tid] = zs;
    __syncthreads();
    for (int off = 128; off > 0; off >>= 1) {
        if (tid < off) {
            r1[tid] += r1[tid + off];
            r2[tid] += r2[tid + off];
            r3[tid] += r3[tid + off];
        }
        __syncthreads();
    }
    if (tid == 0) {
        float* q = &g_part[kb * 3];
        q[0] = r1[0]; q[1] = r2[0]; q[2] = r3[0];
        __threadfence();
        unsigned v = atomicAdd(&g_done, 1u);
        is_last = (v == (unsigned)(TOTBLK - 1));
    }
    __syncthreads();
    if (!is_last) return;
    __threadfence();
    // final reduction over 112 rows x 8 parts (g_part laid out [img][c][part])
    float term = 0.0f;
    if (tid < Nn * Cc) {
        float azt = 0.f, ast = 0.f, azs = 0.f;
        const float* q = &g_part[tid * PARTS * 3];
#pragma unroll
        for (int p = 0; p < PARTS; p++) {
            azt += q[p*3]; ast += q[p*3+1]; azs += q[p*3+2];
        }
        term = ast / azt - logf(azt) + logf(azs);
    }
    __syncthreads();
    r1[tid] = term;
    __syncthreads();
    for (int off = 128; off > 0; off >>= 1) {
        if (tid < off) r1[tid] += r1[tid + off];
        __syncthreads();
    }
    if (tid == 0) {
        out[0] = r1[0] / 112.0f;
        for (int i = 0; i < 24; i++) g_ctr[i * 32] = 0;
        g_done = 0;
    }
}

// ---------------- launch ----------------
extern "C" void kernel_launch(void* const* d_in, const int* in_sizes, int n_in,
                              void* d_out, int out_size) {
    const float* S = (const float*)d_in[0];
    const float* T = (const float*)d_in[1];
    float* out = (float*)d_out;
    k_all<<<GRID, 256>>>(S, T, out);
}